// round 12
// baseline (speedup 1.0000x reference)
#include <cuda_runtime.h>
#include <cuda_fp16.h>
#include <cstdint>

// Propagate: 3-hop fixed-degree(16) CSR SpMM, N=100000, D=64 f32.
// out = A^3 x. indices/values arrive int32/f32 (JAX x64-disabled).
//
// R11: hybrid gather. Model: per-SM L1tex miss tracking (~64 lines) x L2
// latency (~240cyc) caps the LDG gather stream at ~0.27 lines/cyc/SM.
// Split each warp's 32 random lines across two independent tracking domains:
//   - edges 0..7 (both rows): LDG.64 warp-wide gathers (L1tex MSHR path)
//   - edges 8..15 (both rows): 16x cp.async.bulk 128B -> smem (TMA/bulk
//     engine, mbarrier-tracked, no MSHR use)
// fp16 rows (128B = 1 line each), fp32 f32x2 accumulation, 2 rows/warp.

#define N_NODES 100000
#define DEG 16
#define D_FEAT 64
#define D_U2 (D_FEAT / 4)    // 16 uint2 per fp16 row
#define FULL 0xFFFFFFFFu

typedef unsigned long long ull;

__device__ __align__(256) __half g_hx[(size_t)N_NODES * D_FEAT];
__device__ __align__(256) __half g_h0[(size_t)N_NODES * D_FEAT];
__device__ __align__(256) __half g_h1[(size_t)N_NODES * D_FEAT];

__global__ void __launch_bounds__(256) to_half_kernel(
    const float2* __restrict__ in, __half2* __restrict__ out, int n2)
{
    int i = blockIdx.x * blockDim.x + threadIdx.x;
    if (i < n2) {
        float2 v = in[i];
        out[i] = __floats2half2_rn(v.x, v.y);
    }
}

__device__ __forceinline__ uint32_t smem_u32(const void* p) {
    return (uint32_t)__cvta_generic_to_shared(p);
}

template<bool OUT_F32>
__global__ void __launch_bounds__(256) hop_h_kernel(
    const __half* __restrict__ xin,     // fp16 rows, 128B each
    const float* __restrict__ values,
    const int*   __restrict__ indices,
    void* __restrict__ xout,
    int n_nodes)
{
    // Per-warp bulk tile: 16 edges x 128B = 2KB; 8 warps = 16KB (+ mbarriers).
    __shared__ __align__(16) char sbuf[8][16][128];
    __shared__ __align__(8) unsigned long long smbar[8];

    int wib   = threadIdx.x >> 5;
    int lane  = threadIdx.x & 31;
    int gwarp = blockIdx.x * 8 + wib;

    int r0 = gwarp * 2;
    if (r0 >= n_nodes) return;

    uint32_t mbar = smem_u32(&smbar[wib]);
    if (lane == 0) {
        asm volatile("mbarrier.init.shared.b64 [%0], %1;"
                     :: "r"(mbar), "r"(1) : "memory");
    }
    __syncwarp();

    // Lane l holds edge l of the row pair (rows r0,r0+1 own edges
    // [r0*16, r0*16+32), coalesced).
    int eidx = r0 * DEG + lane;
    int   nb = indices[eidx];
    float ev = values[eidx];

    // ---- bulk path: edges 8..15 of each row ----
    if (lane == 0) {
        asm volatile("mbarrier.arrive.expect_tx.shared.b64 _, [%0], %1;"
                     :: "r"(mbar), "r"(2048) : "memory");
    }
    __syncwarp();

    // slot l (l<16): row = l>>3, edge = 8+(l&7); holder lane of that edge:
    //   row0: lane 8+(l&7) ; row1: lane 16+8+(l&7)
    int holder = (lane < 8) ? (lane + 8) : (lane + 16);
    int nbh = __shfl_sync(FULL, nb, holder);
    if (lane < 16) {
        const char* src = (const char*)xin + ((long long)nbh << 7);
        uint32_t dst = smem_u32(&sbuf[wib][lane][0]);
        asm volatile(
            "cp.async.bulk.shared::cluster.global.mbarrier::complete_tx::bytes "
            "[%0], [%1], %2, [%3];"
            :: "r"(dst), "l"(src), "r"(128), "r"(mbar) : "memory");
    }

    // ---- LDG path: edges 0..7 of each row (overlaps with bulk) ----
    int lane16 = lane & 15;
    int src_hi = lane & 16;
    int crow   = lane >> 4;

    ull a01 = 0ull, a23 = 0ull;

#pragma unroll
    for (int e = 0; e < 8; ++e) {
        int   n = __shfl_sync(FULL, nb, src_hi | e);
        float w = __shfl_sync(FULL, ev, src_hi | e);

        uint2 hv = ((const uint2*)xin)[(long long)n * D_U2 + lane16];
        float2 f0 = __half22float2(*reinterpret_cast<__half2*>(&hv.x));
        float2 f1 = __half22float2(*reinterpret_cast<__half2*>(&hv.y));

        ull x01, x23, w2;
        asm("mov.b64 %0, {%1, %2};" : "=l"(x01) : "f"(f0.x), "f"(f0.y));
        asm("mov.b64 %0, {%1, %2};" : "=l"(x23) : "f"(f1.x), "f"(f1.y));
        asm("mov.b64 %0, {%1, %1};" : "=l"(w2)  : "f"(w));
        asm("fma.rn.f32x2 %0, %1, %2, %0;" : "+l"(a01) : "l"(x01), "l"(w2));
        asm("fma.rn.f32x2 %0, %1, %2, %0;" : "+l"(a23) : "l"(x23), "l"(w2));
    }

    // ---- wait for bulk tile, then accumulate edges 8..15 from smem ----
    {
        uint32_t done;
        asm volatile(
            "{\n\t.reg .pred p;\n\t"
            "mbarrier.try_wait.parity.shared.b64 p, [%1], %2;\n\t"
            "selp.b32 %0, 1, 0, p;\n\t}"
            : "=r"(done) : "r"(mbar), "r"(0) : "memory");
        while (!done) {
            asm volatile(
                "{\n\t.reg .pred p;\n\t"
                "mbarrier.try_wait.parity.shared.b64 p, [%1], %2;\n\t"
                "selp.b32 %0, 1, 0, p;\n\t}"
                : "=r"(done) : "r"(mbar), "r"(0) : "memory");
        }
    }
    __syncwarp();

#pragma unroll
    for (int e = 8; e < 16; ++e) {
        float w = __shfl_sync(FULL, ev, src_hi | e);
        // slot = crow*8 + (e-8)
        uint2 hv = *(const uint2*)&sbuf[wib][crow * 8 + (e - 8)][lane16 * 8];
        float2 f0 = __half22float2(*reinterpret_cast<__half2*>(&hv.x));
        float2 f1 = __half22float2(*reinterpret_cast<__half2*>(&hv.y));

        ull x01, x23, w2;
        asm("mov.b64 %0, {%1, %2};" : "=l"(x01) : "f"(f0.x), "f"(f0.y));
        asm("mov.b64 %0, {%1, %2};" : "=l"(x23) : "f"(f1.x), "f"(f1.y));
        asm("mov.b64 %0, {%1, %1};" : "=l"(w2)  : "f"(w));
        asm("fma.rn.f32x2 %0, %1, %2, %0;" : "+l"(a01) : "l"(x01), "l"(w2));
        asm("fma.rn.f32x2 %0, %1, %2, %0;" : "+l"(a23) : "l"(x23), "l"(w2));
    }

    float a0, a1, a2, a3;
    asm("mov.b64 {%0, %1}, %2;" : "=f"(a0), "=f"(a1) : "l"(a01));
    asm("mov.b64 {%0, %1}, %2;" : "=f"(a2), "=f"(a3) : "l"(a23));

    int r = r0 + crow;
    if (r < n_nodes) {
        if (OUT_F32) {
            ((float4*)xout)[(long long)r * 16 + lane16] =
                make_float4(a0, a1, a2, a3);
        } else {
            __half2 o0 = __floats2half2_rn(a0, a1);
            __half2 o1 = __floats2half2_rn(a2, a3);
            uint2 o;
            o.x = *reinterpret_cast<uint32_t*>(&o0);
            o.y = *reinterpret_cast<uint32_t*>(&o1);
            ((uint2*)xout)[(long long)r * D_U2 + lane16] = o;
        }
    }
}

extern "C" void kernel_launch(void* const* d_in, const int* in_sizes, int n_in,
                              void* d_out, int out_size)
{
    const float* x       = (const float*)d_in[0];   // [N, 64] f32
    const float* values  = (const float*)d_in[1];   // [E] f32
    // d_in[2] = indptr — fixed stride DEG, unused
    const int*   indices = (const int*)d_in[3];     // [E] int32
    float* out = (float*)d_out;

    int n_nodes = in_sizes[0] / D_FEAT;

    __half* hx; __half* h0; __half* h1;
    cudaGetSymbolAddress((void**)&hx, g_hx);
    cudaGetSymbolAddress((void**)&h0, g_h0);
    cudaGetSymbolAddress((void**)&h1, g_h1);

    int n2 = n_nodes * D_FEAT / 2;
    int cthreads = 256;
    int cblocks = (n2 + cthreads - 1) / cthreads;
    to_half_kernel<<<cblocks, cthreads>>>((const float2*)x, (__half2*)hx, n2);

    int threads = 256;
    int rows_per_block = (threads / 32) * 2;   // 2 rows per warp
    int blocks = (n_nodes + rows_per_block - 1) / rows_per_block;

    hop_h_kernel<false><<<blocks, threads>>>(hx, values, indices,
                                             (void*)h0, n_nodes);
    hop_h_kernel<false><<<blocks, threads>>>(h0, values, indices,
                                             (void*)h1, n_nodes);
    hop_h_kernel<true><<<blocks, threads>>>(h1, values, indices,
                                            (void*)out, n_nodes);
}

// round 15
// speedup vs baseline: 1.2967x; 1.2967x over previous
#include <cuda_runtime.h>
#include <cuda_fp16.h>
#include <cstdint>

// Propagate: 3-hop fixed-degree(16) CSR SpMM, N=100000, D=64 f32.
// out = A^3 x. indices/values arrive int32/f32 (JAX x64-disabled).
//
// R12 = R7 body (best, 67.6us) + Programmatic Dependent Launch:
// each kernel triggers launch_dependents at entry, so the NEXT kernel's
// edge-stream prelude (independent of this kernel's output) overlaps with
// this kernel's gather/store phase and tail wave. griddepcontrol.wait
// guards the first dependent read (the feature gathers).
// Gather body: fp16 rows, LDG.128 fetching 2 edges x 2 rows (4 random
// 128B lines/instr), f32x2 accumulation, 2 rows/warp (50k warps).

#define N_NODES 100000
#define DEG 16
#define D_FEAT 64
#define FULL 0xFFFFFFFFu

typedef unsigned long long ull;

__device__ __align__(256) __half g_hx[(size_t)N_NODES * D_FEAT];
__device__ __align__(256) __half g_h0[(size_t)N_NODES * D_FEAT];
__device__ __align__(256) __half g_h1[(size_t)N_NODES * D_FEAT];

__global__ void __launch_bounds__(256) to_half_kernel(
    const float2* __restrict__ in, __half2* __restrict__ out, int n2)
{
    asm volatile("griddepcontrol.launch_dependents;");
    int i = blockIdx.x * blockDim.x + threadIdx.x;
    if (i < n2) {
        float2 v = in[i];
        out[i] = __floats2half2_rn(v.x, v.y);
    }
}

template<bool OUT_F32>
__global__ void __launch_bounds__(256) hop_h_kernel(
    const uint4* __restrict__ xin,      // fp16 rows: 8 uint4 (16B) per row
    const float* __restrict__ values,
    const int*   __restrict__ indices,
    void* __restrict__ xout,
    int n_nodes)
{
    // Let the next kernel in the chain begin its (independent) prelude now.
    asm volatile("griddepcontrol.launch_dependents;");

    int gwarp = (blockIdx.x * blockDim.x + threadIdx.x) >> 5;
    int lane  = threadIdx.x & 31;

    int r0 = gwarp * 2;
    if (r0 >= n_nodes) {
        asm volatile("griddepcontrol.wait;");
        return;
    }

    int sub    = (lane >> 3) & 1;   // edge parity this lane handles
    int feat8  = lane & 7;          // 16B feature slice
    int src_hi = lane & 16;         // 0 => row r0 edges, 16 => row r0+1

    // Prelude: edge loads — independent of the previous kernel's output.
    int eidx     = r0 * DEG + lane;
    int   nb_idx = indices[eidx];
    float ev     = values[eidx];

    // Previous kernel's stores must be visible before gathering.
    asm volatile("griddepcontrol.wait;");

    ull a01 = 0ull, a23 = 0ull, a45 = 0ull, a67 = 0ull;

#pragma unroll
    for (int i = 0; i < 8; ++i) {
        int   src = src_hi | (2 * i + sub);
        int   nb  = __shfl_sync(FULL, nb_idx, src);
        float w   = __shfl_sync(FULL, ev,     src);

        uint4 hv = xin[nb * 8 + feat8];        // 16B = 8 fp16 feats

        float2 f0 = __half22float2(*reinterpret_cast<__half2*>(&hv.x));
        float2 f1 = __half22float2(*reinterpret_cast<__half2*>(&hv.y));
        float2 f2 = __half22float2(*reinterpret_cast<__half2*>(&hv.z));
        float2 f3 = __half22float2(*reinterpret_cast<__half2*>(&hv.w));

        ull x01, x23, x45, x67, w2;
        asm("mov.b64 %0, {%1, %2};" : "=l"(x01) : "f"(f0.x), "f"(f0.y));
        asm("mov.b64 %0, {%1, %2};" : "=l"(x23) : "f"(f1.x), "f"(f1.y));
        asm("mov.b64 %0, {%1, %2};" : "=l"(x45) : "f"(f2.x), "f"(f2.y));
        asm("mov.b64 %0, {%1, %2};" : "=l"(x67) : "f"(f3.x), "f"(f3.y));
        asm("mov.b64 %0, {%1, %1};" : "=l"(w2)  : "f"(w));

        asm("fma.rn.f32x2 %0, %1, %2, %0;" : "+l"(a01) : "l"(x01), "l"(w2));
        asm("fma.rn.f32x2 %0, %1, %2, %0;" : "+l"(a23) : "l"(x23), "l"(w2));
        asm("fma.rn.f32x2 %0, %1, %2, %0;" : "+l"(a45) : "l"(x45), "l"(w2));
        asm("fma.rn.f32x2 %0, %1, %2, %0;" : "+l"(a67) : "l"(x67), "l"(w2));
    }

    float a[8];
    asm("mov.b64 {%0, %1}, %2;" : "=f"(a[0]), "=f"(a[1]) : "l"(a01));
    asm("mov.b64 {%0, %1}, %2;" : "=f"(a[2]), "=f"(a[3]) : "l"(a23));
    asm("mov.b64 {%0, %1}, %2;" : "=f"(a[4]), "=f"(a[5]) : "l"(a45));
    asm("mov.b64 {%0, %1}, %2;" : "=f"(a[6]), "=f"(a[7]) : "l"(a67));

    // Lanes l and l^8 hold the same feature slice over disjoint edge halves.
#pragma unroll
    for (int k = 0; k < 8; ++k)
        a[k] += __shfl_xor_sync(FULL, a[k], 8);

    if ((lane & 8) == 0) {
        int r = r0 + (lane >> 4);
        if (r < n_nodes) {
            if (OUT_F32) {
                float4* o = (float4*)xout;
                o[(long long)r * 16 + feat8 * 2 + 0] =
                    make_float4(a[0], a[1], a[2], a[3]);
                o[(long long)r * 16 + feat8 * 2 + 1] =
                    make_float4(a[4], a[5], a[6], a[7]);
            } else {
                __half2 h0 = __floats2half2_rn(a[0], a[1]);
                __half2 h1 = __floats2half2_rn(a[2], a[3]);
                __half2 h2 = __floats2half2_rn(a[4], a[5]);
                __half2 h3 = __floats2half2_rn(a[6], a[7]);
                uint4 o;
                o.x = *reinterpret_cast<uint32_t*>(&h0);
                o.y = *reinterpret_cast<uint32_t*>(&h1);
                o.z = *reinterpret_cast<uint32_t*>(&h2);
                o.w = *reinterpret_cast<uint32_t*>(&h3);
                ((uint4*)xout)[(long long)r * 8 + feat8] = o;
            }
        }
    }
}

template<typename... Args>
static void launch_pdl(void* func, dim3 grid, dim3 block, Args... args)
{
    cudaLaunchAttribute attr[1];
    attr[0].id = cudaLaunchAttributeProgrammaticStreamSerialization;
    attr[0].val.programmaticStreamSerializationAllowed = 1;

    cudaLaunchConfig_t cfg = {};
    cfg.gridDim = grid;
    cfg.blockDim = block;
    cfg.dynamicSmemBytes = 0;
    cfg.stream = 0;
    cfg.attrs = attr;
    cfg.numAttrs = 1;

    void* params[] = { (void*)&args... };
    cudaLaunchKernelExC(&cfg, func, params);
}

extern "C" void kernel_launch(void* const* d_in, const int* in_sizes, int n_in,
                              void* d_out, int out_size)
{
    const float* x       = (const float*)d_in[0];   // [N, 64] f32
    const float* values  = (const float*)d_in[1];   // [E] f32
    // d_in[2] = indptr — fixed stride DEG, unused
    const int*   indices = (const int*)d_in[3];     // [E] int32
    void* out = d_out;

    int n_nodes = in_sizes[0] / D_FEAT;

    __half* hx; __half* h0; __half* h1;
    cudaGetSymbolAddress((void**)&hx, g_hx);
    cudaGetSymbolAddress((void**)&h0, g_h0);
    cudaGetSymbolAddress((void**)&h1, g_h1);

    int n2 = n_nodes * D_FEAT / 2;
    int cthreads = 256;
    int cblocks = (n2 + cthreads - 1) / cthreads;

    int threads = 256;
    int rows_per_block = (threads / 32) * 2;   // 2 rows per warp
    int blocks = (n_nodes + rows_per_block - 1) / rows_per_block;

    const float2*  xf2 = (const float2*)x;
    __half2*       hx2 = (__half2*)hx;
    const uint4*   hx4 = (const uint4*)hx;
    const uint4*   h04 = (const uint4*)h0;
    const uint4*   h14 = (const uint4*)h1;
    void*          vh0 = (void*)h0;
    void*          vh1 = (void*)h1;

    launch_pdl((void*)to_half_kernel, dim3(cblocks), dim3(cthreads),
               xf2, hx2, n2);
    launch_pdl((void*)hop_h_kernel<false>, dim3(blocks), dim3(threads),
               hx4, values, indices, vh0, n_nodes);
    launch_pdl((void*)hop_h_kernel<false>, dim3(blocks), dim3(threads),
               h04, values, indices, vh1, n_nodes);
    launch_pdl((void*)hop_h_kernel<true>, dim3(blocks), dim3(threads),
               h14, values, indices, out, n_nodes);
}